// round 1
// baseline (speedup 1.0000x reference)
#include <cuda_runtime.h>

// ---------------- problem constants ----------------
constexpr int NB  = 256;   // batch
constexpr int NL  = 16;    // max length
constexpr int NH  = 512;   // LSTM hidden
constexpr int ND2 = 1024;  // 2*NH
constexpr int NG4 = 2048;  // 4*NH (lstm gates)
constexpr int NG5 = 5120;  // 5*ND2 (tree gates)

// ---------------- scratch layout ----------------
constexpr long SZ_XREV = (long)NB * NL * NH;
constexpr long SZ_XG   = (long)NB * NL * NG4;
constexpr long SZ_GT   = (long)NB * NG4;
constexpr long SZ_ST   = (long)NB * NH;
constexpr long SZ_SEQ  = (long)NB * NL * NH;
constexpr long SZ_TREE = (long)NB * NL * ND2;
constexpr long SZ_V    = (long)NB * 15 * NG5;
constexpr long SZ_NHC  = (long)NB * 15 * ND2;

constexpr long OFF_XREV   = 0;
constexpr long OFF_XG_F   = OFF_XREV + SZ_XREV;
constexpr long OFF_XG_B   = OFF_XG_F + SZ_XG;
constexpr long OFF_GT_F   = OFF_XG_B + SZ_XG;
constexpr long OFF_GT_B   = OFF_GT_F + SZ_GT;
constexpr long OFF_HST    = OFF_GT_B + SZ_GT;      // 4 states: h_f, h_b, c_f, c_b
constexpr long OFF_HSEQ_F = OFF_HST + 4 * SZ_ST;
constexpr long OFF_HSEQ_B = OFF_HSEQ_F + SZ_SEQ;
constexpr long OFF_CSEQ_F = OFF_HSEQ_B + SZ_SEQ;
constexpr long OFF_CSEQ_B = OFF_CSEQ_F + SZ_SEQ;
constexpr long OFF_HBUF0  = OFF_CSEQ_B + SZ_SEQ;
constexpr long OFF_HBUF1  = OFF_HBUF0 + SZ_TREE;
constexpr long OFF_CBUF0  = OFF_HBUF1 + SZ_TREE;
constexpr long OFF_CBUF1  = OFF_CBUF0 + SZ_TREE;
constexpr long OFF_V      = OFF_CBUF1 + SZ_TREE;
constexpr long OFF_NH     = OFF_V + SZ_V;
constexpr long OFF_NC     = OFF_NH + SZ_NHC;
constexpr long OFF_LOG    = OFF_NC + SZ_NHC;
constexpr long TOTAL_F    = OFF_LOG + (long)NB * 16;

__device__ float g_buf[TOTAL_F];
__device__ int   g_sel[NB];
__device__ int   g_done[NB];

__device__ __forceinline__ float sigm(float x) { return 1.0f / (1.0f + expf(-x)); }

// ---------------- generic fp32 SGEMM ----------------
// C[r, n] = dot(Arow(r)[0..K), W[n, 0..K)) + bias[n] (+ Cinit[r, n])
// Arow(r) base = A + (r / P) * strideB + (r % P) * strideM
// Tiles: 128x128x8, 8x8 per-thread, 256 threads. M,N multiples of 128; K multiple of 8.
__global__ __launch_bounds__(256)
void sgemm_k(const float* __restrict__ A, int P, long strideB, long strideM,
             const float* __restrict__ W, int K,
             const float* __restrict__ bias,
             const float* __restrict__ Cinit, long ciStride,
             float* __restrict__ C, int N)
{
    __shared__ float As[8][128];
    __shared__ float Bs[8][128];
    const int tid = threadIdx.x;
    const int rowBase = blockIdx.y * 128;
    const int colBase = blockIdx.x * 128;
    const int tx = tid & 15;
    const int ty = tid >> 4;
    const int lr = tid >> 1;          // load row within tile (0..127)
    const int lk = (tid & 1) * 4;     // load k offset (0 or 4)

    const int r = rowBase + lr;
    const int bidx = r / P;
    const float* aPtr = A + (long)bidx * strideB + (long)(r - bidx * P) * strideM + lk;
    const float* wPtr = W + (long)(colBase + lr) * K + lk;

    float acc[8][8];
#pragma unroll
    for (int i = 0; i < 8; i++)
#pragma unroll
        for (int j = 0; j < 8; j++) acc[i][j] = 0.0f;

    for (int k0 = 0; k0 < K; k0 += 8) {
        float4 av = *reinterpret_cast<const float4*>(aPtr + k0);
        float4 bv = *reinterpret_cast<const float4*>(wPtr + k0);
        As[lk + 0][lr] = av.x; As[lk + 1][lr] = av.y;
        As[lk + 2][lr] = av.z; As[lk + 3][lr] = av.w;
        Bs[lk + 0][lr] = bv.x; Bs[lk + 1][lr] = bv.y;
        Bs[lk + 2][lr] = bv.z; Bs[lk + 3][lr] = bv.w;
        __syncthreads();
#pragma unroll
        for (int kk = 0; kk < 8; kk++) {
            float4 a0 = *reinterpret_cast<const float4*>(&As[kk][ty * 8]);
            float4 a1 = *reinterpret_cast<const float4*>(&As[kk][ty * 8 + 4]);
            float4 b0 = *reinterpret_cast<const float4*>(&Bs[kk][tx * 8]);
            float4 b1 = *reinterpret_cast<const float4*>(&Bs[kk][tx * 8 + 4]);
            float ra[8] = {a0.x, a0.y, a0.z, a0.w, a1.x, a1.y, a1.z, a1.w};
            float rb[8] = {b0.x, b0.y, b0.z, b0.w, b1.x, b1.y, b1.z, b1.w};
#pragma unroll
            for (int i = 0; i < 8; i++)
#pragma unroll
                for (int j = 0; j < 8; j++)
                    acc[i][j] += ra[i] * rb[j];
        }
        __syncthreads();
    }

#pragma unroll
    for (int i = 0; i < 8; i++) {
        const long row = rowBase + ty * 8 + i;
#pragma unroll
        for (int j = 0; j < 8; j += 4) {
            const int col = colBase + tx * 8 + j;
            float4 v;
            v.x = acc[i][j]; v.y = acc[i][j + 1]; v.z = acc[i][j + 2]; v.w = acc[i][j + 3];
            if (bias) {
                v.x += bias[col]; v.y += bias[col + 1];
                v.z += bias[col + 2]; v.w += bias[col + 3];
            }
            if (Cinit) {
                float4 ci = *reinterpret_cast<const float4*>(Cinit + row * ciStride + col);
                v.x += ci.x; v.y += ci.y; v.z += ci.z; v.w += ci.w;
            }
            *reinterpret_cast<float4*>(C + row * N + col) = v;
        }
    }
}

// ---------------- helper kernels ----------------
__global__ void fill0_k(float* p, long n) {
    long i = (long)blockIdx.x * 256 + threadIdx.x;
    if (i < n) p[i] = 0.0f;
}

__global__ void rev_input_k(const float* __restrict__ x, const int* __restrict__ len,
                            float* __restrict__ xrev)
{
    int idx = blockIdx.x * 256 + threadIdx.x;        // NB*NL*NH
    int j = idx % NH;
    int t2 = idx / NH;
    int t = t2 % NL;
    int b = t2 / NL;
    int ln = len[b];
    int src = (t < ln) ? (ln - 1 - t) : t;
    xrev[idx] = x[((long)b * NL + src) * NH + j];
}

__global__ void lstm_cell_k(const float* __restrict__ gates,
                            float* __restrict__ hstate, float* __restrict__ cstate,
                            float* __restrict__ hseq, float* __restrict__ cseq, int t)
{
    int idx = blockIdx.x * 256 + threadIdx.x;        // NB*NH
    int b = idx >> 9;                                // /512
    int j = idx & (NH - 1);
    const float* g = gates + (long)b * NG4;
    float gi = g[j];
    float gf = g[NH + j];
    float gu = g[2 * NH + j];
    float go = g[3 * NH + j];
    float c = sigm(gf) * cstate[idx] + sigm(gi) * tanhf(gu);
    float h = sigm(go) * tanhf(c);
    cstate[idx] = c;
    hstate[idx] = h;
    long s = ((long)b * NL + t) * NH + j;
    hseq[s] = h;
    cseq[s] = c;
}

__global__ void tree_init_k(const float* __restrict__ hseqf, const float* __restrict__ hseqb,
                            const float* __restrict__ cseqf, const float* __restrict__ cseqb,
                            const int* __restrict__ len,
                            float* __restrict__ hbuf, float* __restrict__ cbuf)
{
    int idx = blockIdx.x * 256 + threadIdx.x;        // NB*NL*ND2
    int j = idx % ND2;
    int t2 = idx / ND2;
    int m = t2 % NL;
    int b = t2 / NL;
    float hv, cv;
    if (j < NH) {
        long s = ((long)b * NL + m) * NH + j;
        hv = hseqf[s]; cv = cseqf[s];
    } else {
        int ln = len[b];
        int rm = (m < ln) ? (ln - 1 - m) : m;
        long s = ((long)b * NL + rm) * NH + (j - NH);
        hv = hseqb[s]; cv = cseqb[s];
    }
    hbuf[idx] = hv;
    cbuf[idx] = cv;
}

// per-pair gates + logits. grid = NB*P blocks, 256 threads.
__global__ void tree_gate_k(const float* __restrict__ v, const float* __restrict__ cbuf,
                            float* __restrict__ nh, float* __restrict__ nc,
                            float* __restrict__ logits, const float* __restrict__ wq, int P)
{
    int blk = blockIdx.x;
    int b = blk / P;
    int m = blk - b * P;
    const float* vr = v + (long)blk * NG5;
    const float* cl = cbuf + ((long)b * NL + m) * ND2;
    const float* cr = cl + ND2;
    float* nhr = nh + ((long)b * 15 + m) * ND2;
    float* ncr = nc + ((long)b * 15 + m) * ND2;
    float dot = 0.0f;
    for (int d = threadIdx.x; d < ND2; d += 256) {
        float vi  = vr[d];
        float vfl = vr[ND2 + d];
        float vfr = vr[2 * ND2 + d];
        float vu  = vr[3 * ND2 + d];
        float vo  = vr[4 * ND2 + d];
        float c = cl[d] * sigm(vfl + 1.0f) + cr[d] * sigm(vfr + 1.0f) + tanhf(vu) * sigm(vi);
        float h = sigm(vo) * tanhf(c);
        ncr[d] = c;
        nhr[d] = h;
        dot += h * wq[d];
    }
    __shared__ float red[8];
#pragma unroll
    for (int o = 16; o > 0; o >>= 1) dot += __shfl_down_sync(0xffffffffu, dot, o);
    if ((threadIdx.x & 31) == 0) red[threadIdx.x >> 5] = dot;
    __syncthreads();
    if (threadIdx.x < 8) {
        float s = red[threadIdx.x];
#pragma unroll
        for (int o = 4; o > 0; o >>= 1) s += __shfl_down_sync(0xffu, s, o);
        if (threadIdx.x == 0) logits[b * 16 + m] = s;
    }
}

// one warp per batch element
__global__ void argmax_k(const float* __restrict__ logits, const int* __restrict__ len,
                         int* __restrict__ sel, int* __restrict__ done, int P, int iter)
{
    int b = blockIdx.x * 8 + (threadIdx.x >> 5);
    int lane = threadIdx.x & 31;
    if (b >= NB) return;
    int ln = len[b];
    float val = -3.4e38f;
    int idx = lane;
    if (lane < P) {
        val = logits[b * 16 + lane];
        if (iter + 1 + lane >= ln) val -= 10000.0f;   // matches ref masking exactly
    }
#pragma unroll
    for (int o = 16; o > 0; o >>= 1) {
        float ov = __shfl_down_sync(0xffffffffu, val, o);
        int oi = __shfl_down_sync(0xffffffffu, idx, o);
        if (ov > val || (ov == val && oi < idx)) { val = ov; idx = oi; }
    }
    if (lane == 0) {
        sel[b] = idx;
        done[b] = (iter + 1 < ln) ? 1 : 0;
    }
}

__global__ void tree_update_k(const float* __restrict__ hold, const float* __restrict__ cold,
                              const float* __restrict__ nh, const float* __restrict__ nc,
                              float* __restrict__ hnew, float* __restrict__ cnew,
                              const int* __restrict__ sel, const int* __restrict__ done, int P)
{
    int idx = blockIdx.x * 256 + threadIdx.x;        // NB*P*ND2
    int d = idx % ND2;
    int t = idx / ND2;
    int m = t % P;
    int b = t / P;
    long obase = (long)b * NL * ND2;
    float hv, cv;
    if (!done[b]) {
        hv = hold[obase + (long)m * ND2 + d];
        cv = cold[obase + (long)m * ND2 + d];
    } else {
        int s = sel[b];
        if (m < s) {
            hv = hold[obase + (long)m * ND2 + d];
            cv = cold[obase + (long)m * ND2 + d];
        } else if (m == s) {
            long nidx = ((long)b * 15 + m) * ND2 + d;
            hv = nh[nidx];
            cv = nc[nidx];
        } else {
            hv = hold[obase + (long)(m + 1) * ND2 + d];
            cv = cold[obase + (long)(m + 1) * ND2 + d];
        }
    }
    hnew[obase + (long)m * ND2 + d] = hv;
    cnew[obase + (long)m * ND2 + d] = cv;
}

__global__ void copy_out_k(const float* __restrict__ hfinal, float* __restrict__ out)
{
    int idx = blockIdx.x * 256 + threadIdx.x;        // NB*ND2
    int b = idx / ND2;
    int d = idx % ND2;
    out[idx] = hfinal[(long)b * NL * ND2 + d];
}

// ---------------- launch ----------------
extern "C" void kernel_launch(void* const* d_in, const int* in_sizes, int n_in,
                              void* d_out, int out_size)
{
    const float* x       = (const float*)d_in[0];
    const int*   len     = (const int*)d_in[1];
    const float* w_ih_f  = (const float*)d_in[2];
    const float* w_hh_f  = (const float*)d_in[3];
    const float* b_f     = (const float*)d_in[4];
    const float* w_ih_b  = (const float*)d_in[5];
    const float* w_hh_b  = (const float*)d_in[6];
    const float* b_b     = (const float*)d_in[7];
    const float* w_comp  = (const float*)d_in[8];
    const float* b_comp  = (const float*)d_in[9];
    const float* w_query = (const float*)d_in[10];
    float* out = (float*)d_out;

    float* S = nullptr;
    cudaGetSymbolAddress((void**)&S, g_buf);
    int* selp = nullptr;
    cudaGetSymbolAddress((void**)&selp, g_sel);
    int* donep = nullptr;
    cudaGetSymbolAddress((void**)&donep, g_done);

    // zero LSTM states (h_f, h_b, c_f, c_b)
    fill0_k<<<(int)((4 * SZ_ST + 255) / 256), 256>>>(S + OFF_HST, 4 * SZ_ST);

    // reversed input for backward LSTM
    rev_input_k<<<(NB * NL * NH) / 256, 256>>>(x, len, S + OFF_XREV);

    // input projections: xg = x @ w_ih^T + b   (M=4096, N=2048, K=512)
    dim3 gproj(NG4 / 128, (NB * NL) / 128);
    sgemm_k<<<gproj, 256>>>(x, 1, NH, 0, w_ih_f, NH, b_f, nullptr, 0, S + OFF_XG_F, NG4);
    sgemm_k<<<gproj, 256>>>(S + OFF_XREV, 1, NH, 0, w_ih_b, NH, b_b, nullptr, 0, S + OFF_XG_B, NG4);

    // recurrent steps
    dim3 grec(NG4 / 128, NB / 128);
    for (int t = 0; t < NL; t++) {
        sgemm_k<<<grec, 256>>>(S + OFF_HST + 0 * SZ_ST, 1, NH, 0, w_hh_f, NH, nullptr,
                               S + OFF_XG_F + (long)t * NG4, (long)NL * NG4, S + OFF_GT_F, NG4);
        sgemm_k<<<grec, 256>>>(S + OFF_HST + 1 * SZ_ST, 1, NH, 0, w_hh_b, NH, nullptr,
                               S + OFF_XG_B + (long)t * NG4, (long)NL * NG4, S + OFF_GT_B, NG4);
        lstm_cell_k<<<(NB * NH) / 256, 256>>>(S + OFF_GT_F, S + OFF_HST + 0 * SZ_ST,
                                              S + OFF_HST + 2 * SZ_ST,
                                              S + OFF_HSEQ_F, S + OFF_CSEQ_F, t);
        lstm_cell_k<<<(NB * NH) / 256, 256>>>(S + OFF_GT_B, S + OFF_HST + 1 * SZ_ST,
                                              S + OFF_HST + 3 * SZ_ST,
                                              S + OFF_HSEQ_B, S + OFF_CSEQ_B, t);
    }

    // init tree buffers: concat fwd + reversed bwd
    tree_init_k<<<(NB * NL * ND2) / 256, 256>>>(S + OFF_HSEQ_F, S + OFF_HSEQ_B,
                                                S + OFF_CSEQ_F, S + OFF_CSEQ_B,
                                                len, S + OFF_HBUF0, S + OFF_CBUF0);

    int cur = 0;
    for (int i = 0; i < 15; i++) {
        int P = 15 - i;
        float* hold = S + (cur ? OFF_HBUF1 : OFF_HBUF0);
        float* cold = S + (cur ? OFF_CBUF1 : OFF_CBUF0);
        float* hnew = S + (cur ? OFF_HBUF0 : OFF_HBUF1);
        float* cnew = S + (cur ? OFF_CBUF0 : OFF_CBUF1);

        // pair GEMM: A row (b,m) = h[b, m..m+2) contiguous (2048 floats), strided rows
        dim3 gv(NG5 / 128, (NB * P) / 128);
        sgemm_k<<<gv, 256>>>(hold, P, (long)NL * ND2, ND2, w_comp, NG4, b_comp,
                             nullptr, 0, S + OFF_V, NG5);

        tree_gate_k<<<NB * P, 256>>>(S + OFF_V, cold, S + OFF_NH, S + OFF_NC,
                                     S + OFF_LOG, w_query, P);
        argmax_k<<<NB / 8, 256>>>(S + OFF_LOG, len, selp, donep, P, i);
        tree_update_k<<<(NB * P * ND2) / 256, 256>>>(hold, cold, S + OFF_NH, S + OFF_NC,
                                                     hnew, cnew, selp, donep, P);
        cur ^= 1;
    }

    copy_out_k<<<(NB * ND2) / 256, 256>>>(S + (cur ? OFF_HBUF1 : OFF_HBUF0), out);
}

// round 2
// speedup vs baseline: 1.9239x; 1.9239x over previous
#include <cuda_runtime.h>

// ---------------- problem constants ----------------
constexpr int NB  = 256;   // batch
constexpr int NL  = 16;    // max length
constexpr int NH  = 512;   // LSTM hidden
constexpr int ND2 = 1024;  // 2*NH
constexpr int NG4 = 2048;  // 4*NH (lstm gates) == 2*ND2 (tree GEMM K)
constexpr int NG5 = 5120;  // 5*ND2 (tree gates)

// ---------------- scratch layout ----------------
constexpr long SZ_XREV = (long)NB * NL * NH;
constexpr long SZ_XG   = (long)NB * NL * NG4;
constexpr long SZ_GT   = (long)NB * NG4;
constexpr long SZ_ST   = (long)NB * NH;
constexpr long SZ_SEQ  = (long)NB * NL * NH;
constexpr long SZ_TREE = (long)NB * NL * ND2;
constexpr long SZ_V    = (long)NB * 15 * NG5;
constexpr long SZ_VS   = (long)512 * NG5;
constexpr long SZ_NHC  = (long)NB * 15 * ND2;
constexpr long SZ_LOG  = (long)NB * 16;

constexpr long OFF_XREV   = 0;
constexpr long OFF_XG_F   = OFF_XREV + SZ_XREV;
constexpr long OFF_XG_B   = OFF_XG_F + SZ_XG;
constexpr long OFF_GT_F   = OFF_XG_B + SZ_XG;
constexpr long OFF_GT_B   = OFF_GT_F + SZ_GT;
constexpr long OFF_HST    = OFF_GT_B + SZ_GT;      // 4 states: h_f, h_b, c_f, c_b
constexpr long OFF_HSEQ_F = OFF_HST + 4 * SZ_ST;
constexpr long OFF_HSEQ_B = OFF_HSEQ_F + SZ_SEQ;
constexpr long OFF_CSEQ_F = OFF_HSEQ_B + SZ_SEQ;
constexpr long OFF_CSEQ_B = OFF_CSEQ_F + SZ_SEQ;
constexpr long OFF_HBUF0  = OFF_CSEQ_B + SZ_SEQ;
constexpr long OFF_HBUF1  = OFF_HBUF0 + SZ_TREE;
constexpr long OFF_CBUF0  = OFF_HBUF1 + SZ_TREE;
constexpr long OFF_CBUF1  = OFF_CBUF0 + SZ_TREE;
constexpr long OFF_V      = OFF_CBUF1 + SZ_TREE;
constexpr long OFF_VS     = OFF_V + SZ_V;
constexpr long OFF_NH0    = OFF_VS + SZ_VS;
constexpr long OFF_NH1    = OFF_NH0 + SZ_NHC;
constexpr long OFF_NC0    = OFF_NH1 + SZ_NHC;
constexpr long OFF_NC1    = OFF_NC0 + SZ_NHC;
constexpr long OFF_LOG0   = OFF_NC1 + SZ_NHC;
constexpr long OFF_LOG1   = OFF_LOG0 + SZ_LOG;
constexpr long TOTAL_F    = OFF_LOG1 + SZ_LOG;

__device__ float g_buf[TOTAL_F];
__device__ int   g_sel[NB];
__device__ int   g_done[NB];
__device__ int   g_rowidx[512];
__device__ int   g_valid[512];
__device__ int   g_mr[512];

__device__ __forceinline__ float sigm(float x) { return 1.0f / (1.0f + expf(-x)); }

// ---------------- generic fp32 SGEMM body ----------------
// C[r, n] = dot(Arow(r)[0..K), W[n, 0..K)) + bias[n] (+ Cinit[r, n])
// Arow(r) base:
//   rowIdx != null : A + rowIdx[r] * strideM
//   else           : A + (r / P) * strideB + (r % P) * strideM
// Tiles: 128x128x8, 8x8 per-thread, 256 threads. M,N multiples of 128; K multiple of 8.
__device__ __forceinline__
void sgemm_body(const float* __restrict__ A, int P, long strideB, long strideM,
                const int* __restrict__ rowIdx,
                const float* __restrict__ W, int K,
                const float* __restrict__ bias,
                const float* __restrict__ Cinit, long ciStride,
                float* __restrict__ C, int N)
{
    __shared__ float As[8][128];
    __shared__ float Bs[8][128];
    const int tid = threadIdx.x;
    const int rowBase = blockIdx.y * 128;
    const int colBase = blockIdx.x * 128;
    const int tx = tid & 15;
    const int ty = tid >> 4;
    const int lr = tid >> 1;          // load row within tile (0..127)
    const int lk = (tid & 1) * 4;     // load k offset (0 or 4)

    const int r = rowBase + lr;
    const float* aPtr;
    if (rowIdx) {
        aPtr = A + (long)rowIdx[r] * strideM + lk;
    } else {
        const int bidx = r / P;
        aPtr = A + (long)bidx * strideB + (long)(r - bidx * P) * strideM + lk;
    }
    const float* wPtr = W + (long)(colBase + lr) * K + lk;

    float acc[8][8];
#pragma unroll
    for (int i = 0; i < 8; i++)
#pragma unroll
        for (int j = 0; j < 8; j++) acc[i][j] = 0.0f;

    for (int k0 = 0; k0 < K; k0 += 8) {
        float4 av = *reinterpret_cast<const float4*>(aPtr + k0);
        float4 bv = *reinterpret_cast<const float4*>(wPtr + k0);
        As[lk + 0][lr] = av.x; As[lk + 1][lr] = av.y;
        As[lk + 2][lr] = av.z; As[lk + 3][lr] = av.w;
        Bs[lk + 0][lr] = bv.x; Bs[lk + 1][lr] = bv.y;
        Bs[lk + 2][lr] = bv.z; Bs[lk + 3][lr] = bv.w;
        __syncthreads();
#pragma unroll
        for (int kk = 0; kk < 8; kk++) {
            float4 a0 = *reinterpret_cast<const float4*>(&As[kk][ty * 8]);
            float4 a1 = *reinterpret_cast<const float4*>(&As[kk][ty * 8 + 4]);
            float4 b0 = *reinterpret_cast<const float4*>(&Bs[kk][tx * 8]);
            float4 b1 = *reinterpret_cast<const float4*>(&Bs[kk][tx * 8 + 4]);
            float ra[8] = {a0.x, a0.y, a0.z, a0.w, a1.x, a1.y, a1.z, a1.w};
            float rb[8] = {b0.x, b0.y, b0.z, b0.w, b1.x, b1.y, b1.z, b1.w};
#pragma unroll
            for (int i = 0; i < 8; i++)
#pragma unroll
                for (int j = 0; j < 8; j++)
                    acc[i][j] += ra[i] * rb[j];
        }
        __syncthreads();
    }

#pragma unroll
    for (int i = 0; i < 8; i++) {
        const long row = rowBase + ty * 8 + i;
#pragma unroll
        for (int j = 0; j < 8; j += 4) {
            const int col = colBase + tx * 8 + j;
            float4 v;
            v.x = acc[i][j]; v.y = acc[i][j + 1]; v.z = acc[i][j + 2]; v.w = acc[i][j + 3];
            if (bias) {
                v.x += bias[col]; v.y += bias[col + 1];
                v.z += bias[col + 2]; v.w += bias[col + 3];
            }
            if (Cinit) {
                float4 ci = *reinterpret_cast<const float4*>(Cinit + row * ciStride + col);
                v.x += ci.x; v.y += ci.y; v.z += ci.z; v.w += ci.w;
            }
            *reinterpret_cast<float4*>(C + row * N + col) = v;
        }
    }
}

__global__ __launch_bounds__(256)
void sgemm_k(const float* __restrict__ A, int P, long strideB, long strideM,
             const int* __restrict__ rowIdx,
             const float* __restrict__ W, int K,
             const float* __restrict__ bias,
             const float* __restrict__ Cinit, long ciStride,
             float* __restrict__ C, int N)
{
    sgemm_body(A, P, strideB, strideM, rowIdx, W, K, bias, Cinit, ciStride, C, N);
}

// dual variant: blockIdx.z selects between two independent GEMMs of identical geometry
__global__ __launch_bounds__(256)
void sgemm_dual_k(const float* __restrict__ A0, const float* __restrict__ A1,
                  int P, long strideB, long strideM,
                  const float* __restrict__ W0, const float* __restrict__ W1, int K,
                  const float* __restrict__ bias0, const float* __restrict__ bias1,
                  const float* __restrict__ Ci0, const float* __restrict__ Ci1, long ciStride,
                  float* __restrict__ C0, float* __restrict__ C1, int N)
{
    if (blockIdx.z == 0)
        sgemm_body(A0, P, strideB, strideM, nullptr, W0, K, bias0, Ci0, ciStride, C0, N);
    else
        sgemm_body(A1, P, strideB, strideM, nullptr, W1, K, bias1, Ci1, ciStride, C1, N);
}

// ---------------- helper kernels ----------------
__global__ void fill0_k(float* p, long n) {
    long i = (long)blockIdx.x * 256 + threadIdx.x;
    if (i < n) p[i] = 0.0f;
}

__global__ void rev_input_k(const float* __restrict__ x, const int* __restrict__ len,
                            float* __restrict__ xrev)
{
    int idx = blockIdx.x * 256 + threadIdx.x;        // NB*NL*NH
    int j = idx % NH;
    int t2 = idx / NH;
    int t = t2 % NL;
    int b = t2 / NL;
    int ln = len[b];
    int src = (t < ln) ? (ln - 1 - t) : t;
    xrev[idx] = x[((long)b * NL + src) * NH + j];
}

// fused fwd+bwd LSTM cell: idx covers 2*NB*NH, first half fwd
__global__ void lstm_cell2_k(const float* __restrict__ gf, const float* __restrict__ gb,
                             float* __restrict__ hf, float* __restrict__ hb,
                             float* __restrict__ cf, float* __restrict__ cb,
                             float* __restrict__ hsf, float* __restrict__ hsb,
                             float* __restrict__ csf, float* __restrict__ csb, int t)
{
    int gidx = blockIdx.x * 256 + threadIdx.x;       // 2*NB*NH
    int half = gidx >= NB * NH;
    int idx = gidx - half * NB * NH;
    int b = idx >> 9;
    int j = idx & (NH - 1);
    const float* g = (half ? gb : gf) + (long)b * NG4;
    float* hstate = half ? hb : hf;
    float* cstate = half ? cb : cf;
    float* hseq   = half ? hsb : hsf;
    float* cseq   = half ? csb : csf;
    float gi = g[j];
    float gfo = g[NH + j];
    float gu = g[2 * NH + j];
    float go = g[3 * NH + j];
    float c = sigm(gfo) * cstate[idx] + sigm(gi) * tanhf(gu);
    float h = sigm(go) * tanhf(c);
    cstate[idx] = c;
    hstate[idx] = h;
    long s = ((long)b * NL + t) * NH + j;
    hseq[s] = h;
    cseq[s] = c;
}

__global__ void tree_init_k(const float* __restrict__ hseqf, const float* __restrict__ hseqb,
                            const float* __restrict__ cseqf, const float* __restrict__ cseqb,
                            const int* __restrict__ len,
                            float* __restrict__ hbuf, float* __restrict__ cbuf)
{
    int idx = blockIdx.x * 256 + threadIdx.x;        // NB*NL*ND2
    int j = idx % ND2;
    int t2 = idx / ND2;
    int m = t2 % NL;
    int b = t2 / NL;
    float hv, cv;
    if (j < NH) {
        long s = ((long)b * NL + m) * NH + j;
        hv = hseqf[s]; cv = cseqf[s];
    } else {
        int ln = len[b];
        int rm = (m < ln) ? (ln - 1 - m) : m;
        long s = ((long)b * NL + rm) * NH + (j - NH);
        hv = hseqb[s]; cv = cseqb[s];
    }
    hbuf[idx] = hv;
    cbuf[idx] = cv;
}

// full per-pair gates + logits (iter 0 only). grid = NB*15 blocks.
__global__ void tree_gate_full_k(const float* __restrict__ v, const float* __restrict__ cbuf,
                                 float* __restrict__ nh, float* __restrict__ nc,
                                 float* __restrict__ logits, const float* __restrict__ wq)
{
    int blk = blockIdx.x;
    int b = blk / 15;
    int m = blk - b * 15;
    const float* vr = v + (long)blk * NG5;
    const float* cl = cbuf + ((long)b * NL + m) * ND2;
    const float* cr = cl + ND2;
    float* nhr = nh + ((long)b * 15 + m) * ND2;
    float* ncr = nc + ((long)b * 15 + m) * ND2;
    float dot = 0.0f;
    for (int d = threadIdx.x; d < ND2; d += 256) {
        float vi  = vr[d];
        float vfl = vr[ND2 + d];
        float vfr = vr[2 * ND2 + d];
        float vu  = vr[3 * ND2 + d];
        float vo  = vr[4 * ND2 + d];
        float c = cl[d] * sigm(vfl + 1.0f) + cr[d] * sigm(vfr + 1.0f) + tanhf(vu) * sigm(vi);
        float h = sigm(vo) * tanhf(c);
        ncr[d] = c;
        nhr[d] = h;
        dot += h * wq[d];
    }
    __shared__ float red[8];
#pragma unroll
    for (int o = 16; o > 0; o >>= 1) dot += __shfl_down_sync(0xffffffffu, dot, o);
    if ((threadIdx.x & 31) == 0) red[threadIdx.x >> 5] = dot;
    __syncthreads();
    if (threadIdx.x < 8) {
        float s = red[threadIdx.x];
#pragma unroll
        for (int o = 4; o > 0; o >>= 1) s += __shfl_down_sync(0xffu, s, o);
        if (threadIdx.x == 0) logits[b * 16 + m] = s;
    }
}

// incremental gates for changed pairs only. grid = 512 blocks (b*2+w).
__global__ void tree_gate_small_k(const float* __restrict__ v, const float* __restrict__ cbuf,
                                  float* __restrict__ nh, float* __restrict__ nc,
                                  float* __restrict__ logits, const float* __restrict__ wq,
                                  const int* __restrict__ valid, const int* __restrict__ mr)
{
    int r = blockIdx.x;
    if (!valid[r]) return;
    int b = r >> 1;
    int m = mr[r];
    const float* vr = v + (long)r * NG5;
    const float* cl = cbuf + ((long)b * NL + m) * ND2;
    const float* cr = cl + ND2;
    float* nhr = nh + ((long)b * 15 + m) * ND2;
    float* ncr = nc + ((long)b * 15 + m) * ND2;
    float dot = 0.0f;
    for (int d = threadIdx.x; d < ND2; d += 256) {
        float vi  = vr[d];
        float vfl = vr[ND2 + d];
        float vfr = vr[2 * ND2 + d];
        float vu  = vr[3 * ND2 + d];
        float vo  = vr[4 * ND2 + d];
        float c = cl[d] * sigm(vfl + 1.0f) + cr[d] * sigm(vfr + 1.0f) + tanhf(vu) * sigm(vi);
        float h = sigm(vo) * tanhf(c);
        ncr[d] = c;
        nhr[d] = h;
        dot += h * wq[d];
    }
    __shared__ float red[8];
#pragma unroll
    for (int o = 16; o > 0; o >>= 1) dot += __shfl_down_sync(0xffffffffu, dot, o);
    if ((threadIdx.x & 31) == 0) red[threadIdx.x >> 5] = dot;
    __syncthreads();
    if (threadIdx.x < 8) {
        float s = red[threadIdx.x];
#pragma unroll
        for (int o = 4; o > 0; o >>= 1) s += __shfl_down_sync(0xffu, s, o);
        if (threadIdx.x == 0) logits[b * 16 + m] = s;
    }
}

// one warp per batch element
__global__ void argmax_k(const float* __restrict__ logits, const int* __restrict__ len,
                         int* __restrict__ sel, int* __restrict__ done, int P, int iter)
{
    int b = blockIdx.x * 8 + (threadIdx.x >> 5);
    int lane = threadIdx.x & 31;
    if (b >= NB) return;
    int ln = len[b];
    float val = -3.4e38f;
    int idx = lane;
    if (lane < P) {
        val = logits[b * 16 + lane];
        if (iter + 1 + lane >= ln) val -= 10000.0f;   // matches ref masking exactly
    }
#pragma unroll
    for (int o = 16; o > 0; o >>= 1) {
        float ov = __shfl_down_sync(0xffffffffu, val, o);
        int oi = __shfl_down_sync(0xffffffffu, idx, o);
        if (ov > val || (ov == val && oi < idx)) { val = ov; idx = oi; }
    }
    if (lane == 0) {
        sel[b] = idx;
        done[b] = (iter + 1 < ln) ? 1 : 0;
    }
}

__global__ void tree_update_k(const float* __restrict__ hold, const float* __restrict__ cold,
                              const float* __restrict__ nh, const float* __restrict__ nc,
                              float* __restrict__ hnew, float* __restrict__ cnew,
                              const int* __restrict__ sel, const int* __restrict__ done, int P)
{
    int idx = blockIdx.x * 256 + threadIdx.x;        // NB*P*ND2
    int d = idx % ND2;
    int t = idx / ND2;
    int m = t % P;
    int b = t / P;
    long obase = (long)b * NL * ND2;
    float hv, cv;
    if (!done[b]) {
        hv = hold[obase + (long)m * ND2 + d];
        cv = cold[obase + (long)m * ND2 + d];
    } else {
        int s = sel[b];
        if (m < s) {
            hv = hold[obase + (long)m * ND2 + d];
            cv = cold[obase + (long)m * ND2 + d];
        } else if (m == s) {
            long nidx = ((long)b * 15 + m) * ND2 + d;
            hv = nh[nidx];
            cv = nc[nidx];
        } else {
            hv = hold[obase + (long)(m + 1) * ND2 + d];
            cv = cold[obase + (long)(m + 1) * ND2 + d];
        }
    }
    hnew[obase + (long)m * ND2 + d] = hv;
    cnew[obase + (long)m * ND2 + d] = cv;
}

// shift nh/nc/logit caches: new pair m <- old pair (done && m>s) ? m+1 : m
__global__ void shift_cache_k(const float* __restrict__ nh0, const float* __restrict__ nc0,
                              const float* __restrict__ lg0,
                              float* __restrict__ nh1, float* __restrict__ nc1,
                              float* __restrict__ lg1,
                              const int* __restrict__ sel, const int* __restrict__ done, int newP)
{
    int idx = blockIdx.x * 256 + threadIdx.x;        // NB*newP*ND2
    int d = idx % ND2;
    int t = idx / ND2;
    int m = t % newP;
    int b = t / newP;
    int s = sel[b];
    int src = (done[b] && m > s) ? m + 1 : m;
    long di = ((long)b * 15 + m) * ND2 + d;
    long si = ((long)b * 15 + src) * ND2 + d;
    nh1[di] = nh0[si];
    nc1[di] = nc0[si];
    if (d == 0) lg1[b * 16 + m] = lg0[b * 16 + src];
}

// compute gather rows for the incremental GEMM (1 block, 512 threads)
__global__ void rowoff_k(const int* __restrict__ sel, const int* __restrict__ done,
                         int* __restrict__ rowIdx, int* __restrict__ valid,
                         int* __restrict__ mr, int P)
{
    int r = threadIdx.x;   // 0..511
    int b = r >> 1;
    int w = r & 1;
    int s = sel[b];
    int newP = P - 1;
    int m = s - 1 + w;
    int v = (done[b] && m >= 0 && m <= newP - 1) ? 1 : 0;
    int mc = m < 0 ? 0 : (m > newP - 1 ? newP - 1 : m);
    rowIdx[r] = b * NL + mc;
    valid[r] = v;
    mr[r] = mc;
}

__global__ void copy_out_k(const float* __restrict__ hfinal, float* __restrict__ out)
{
    int idx = blockIdx.x * 256 + threadIdx.x;        // NB*ND2
    int b = idx / ND2;
    int d = idx % ND2;
    out[idx] = hfinal[(long)b * NL * ND2 + d];
}

// ---------------- launch ----------------
extern "C" void kernel_launch(void* const* d_in, const int* in_sizes, int n_in,
                              void* d_out, int out_size)
{
    const float* x       = (const float*)d_in[0];
    const int*   len     = (const int*)d_in[1];
    const float* w_ih_f  = (const float*)d_in[2];
    const float* w_hh_f  = (const float*)d_in[3];
    const float* b_f     = (const float*)d_in[4];
    const float* w_ih_b  = (const float*)d_in[5];
    const float* w_hh_b  = (const float*)d_in[6];
    const float* b_b     = (const float*)d_in[7];
    const float* w_comp  = (const float*)d_in[8];
    const float* b_comp  = (const float*)d_in[9];
    const float* w_query = (const float*)d_in[10];
    float* out = (float*)d_out;

    float* S = nullptr;
    cudaGetSymbolAddress((void**)&S, g_buf);
    int* selp = nullptr;   cudaGetSymbolAddress((void**)&selp, g_sel);
    int* donep = nullptr;  cudaGetSymbolAddress((void**)&donep, g_done);
    int* rowp = nullptr;   cudaGetSymbolAddress((void**)&rowp, g_rowidx);
    int* valp = nullptr;   cudaGetSymbolAddress((void**)&valp, g_valid);
    int* mrp = nullptr;    cudaGetSymbolAddress((void**)&mrp, g_mr);

    // zero LSTM states (h_f, h_b, c_f, c_b)
    fill0_k<<<(int)((4 * SZ_ST + 255) / 256), 256>>>(S + OFF_HST, 4 * SZ_ST);

    // reversed input for backward LSTM
    rev_input_k<<<(NB * NL * NH) / 256, 256>>>(x, len, S + OFF_XREV);

    // fused input projections: xg = x @ w_ih^T + b   (M=4096, N=2048, K=512) x2
    dim3 gproj(NG4 / 128, (NB * NL) / 128, 2);
    sgemm_dual_k<<<gproj, 256>>>(x, S + OFF_XREV, 1, NH, NH,
                                 w_ih_f, w_ih_b, NH, b_f, b_b,
                                 nullptr, nullptr, 0,
                                 S + OFF_XG_F, S + OFF_XG_B, NG4);

    // recurrent steps (fwd+bwd fused per step)
    dim3 grec(NG4 / 128, NB / 128, 2);
    for (int t = 0; t < NL; t++) {
        sgemm_dual_k<<<grec, 256>>>(S + OFF_HST + 0 * SZ_ST, S + OFF_HST + 1 * SZ_ST,
                                    1, NH, NH,
                                    w_hh_f, w_hh_b, NH, nullptr, nullptr,
                                    S + OFF_XG_F + (long)t * NG4, S + OFF_XG_B + (long)t * NG4,
                                    (long)NL * NG4,
                                    S + OFF_GT_F, S + OFF_GT_B, NG4);
        lstm_cell2_k<<<(2 * NB * NH) / 256, 256>>>(S + OFF_GT_F, S + OFF_GT_B,
                                                   S + OFF_HST + 0 * SZ_ST, S + OFF_HST + 1 * SZ_ST,
                                                   S + OFF_HST + 2 * SZ_ST, S + OFF_HST + 3 * SZ_ST,
                                                   S + OFF_HSEQ_F, S + OFF_HSEQ_B,
                                                   S + OFF_CSEQ_F, S + OFF_CSEQ_B, t);
    }

    // init tree buffers: concat fwd + reversed bwd
    tree_init_k<<<(NB * NL * ND2) / 256, 256>>>(S + OFF_HSEQ_F, S + OFF_HSEQ_B,
                                                S + OFF_CSEQ_F, S + OFF_CSEQ_B,
                                                len, S + OFF_HBUF0, S + OFF_CBUF0);

    // iter-0 full pair GEMM + gates (15 pairs per batch)
    {
        dim3 gv(NG5 / 128, (NB * 15) / 128);
        sgemm_k<<<gv, 256>>>(S + OFF_HBUF0, 15, (long)NL * ND2, ND2, nullptr,
                             w_comp, NG4, b_comp, nullptr, 0, S + OFF_V, NG5);
        tree_gate_full_k<<<NB * 15, 256>>>(S + OFF_V, S + OFF_CBUF0,
                                           S + OFF_NH0, S + OFF_NC0, S + OFF_LOG0, w_query);
    }

    int cur = 0;   // slot buffer ping-pong
    int cc = 0;    // cache ping-pong
    for (int i = 0; i < 15; i++) {
        int P = 15 - i;
        float* hold = S + (cur ? OFF_HBUF1 : OFF_HBUF0);
        float* cold = S + (cur ? OFF_CBUF1 : OFF_CBUF0);
        float* hnew = S + (cur ? OFF_HBUF0 : OFF_HBUF1);
        float* cnew = S + (cur ? OFF_CBUF0 : OFF_CBUF1);
        float* nhc  = S + (cc ? OFF_NH1 : OFF_NH0);
        float* ncc  = S + (cc ? OFF_NC1 : OFF_NC0);
        float* lgc  = S + (cc ? OFF_LOG1 : OFF_LOG0);
        float* nhn  = S + (cc ? OFF_NH0 : OFF_NH1);
        float* ncn  = S + (cc ? OFF_NC0 : OFF_NC1);
        float* lgn  = S + (cc ? OFF_LOG0 : OFF_LOG1);

        argmax_k<<<NB / 8, 256>>>(lgc, len, selp, donep, P, i);
        tree_update_k<<<(NB * P * ND2) / 256, 256>>>(hold, cold, nhc, ncc,
                                                     hnew, cnew, selp, donep, P);
        if (i < 14) {
            int newP = P - 1;
            shift_cache_k<<<(NB * newP * ND2) / 256, 256>>>(nhc, ncc, lgc,
                                                            nhn, ncn, lgn,
                                                            selp, donep, newP);
            rowoff_k<<<1, 512>>>(selp, donep, rowp, valp, mrp, P);
            // incremental GEMM over the ≤2 changed pairs per batch (M=512)
            dim3 gs(NG5 / 128, 512 / 128);
            sgemm_k<<<gs, 256>>>(hnew, 1, 0, ND2, rowp,
                                 w_comp, NG4, b_comp, nullptr, 0, S + OFF_VS, NG5);
            tree_gate_small_k<<<512, 256>>>(S + OFF_VS, cnew, nhn, ncn, lgn,
                                            w_query, valp, mrp);
            cc ^= 1;
        }
        cur ^= 1;
    }

    copy_out_k<<<(NB * ND2) / 256, 256>>>(S + (cur ? OFF_HBUF1 : OFF_HBUF0), out);
}

// round 3
// speedup vs baseline: 2.7467x; 1.4277x over previous
#include <cuda_runtime.h>

// ---------------- problem constants ----------------
constexpr int NB  = 256;   // batch
constexpr int NL  = 16;    // max length
constexpr int NH  = 512;   // LSTM hidden
constexpr int ND2 = 1024;  // 2*NH
constexpr int NG4 = 2048;  // 4*NH (lstm gates) == 2*ND2 (tree GEMM K)
constexpr int NG5 = 5120;  // 5*ND2 (tree gates)
constexpr int NSPLIT = 4;  // split-K factor for incremental GEMM

// ---------------- scratch layout ----------------
constexpr long SZ_XREV = (long)NB * NL * NH;
constexpr long SZ_XG   = (long)NB * NL * NG4;
constexpr long SZ_GT   = (long)NB * NG4;
constexpr long SZ_ST   = (long)NB * NH;
constexpr long SZ_SEQ  = (long)NB * NL * NH;
constexpr long SZ_TREE = (long)NB * NL * ND2;
constexpr long SZ_V    = (long)NB * 15 * NG5;
constexpr long SZ_VP   = (long)NSPLIT * 512 * NG5;
constexpr long SZ_NHC  = (long)NB * 15 * ND2;
constexpr long SZ_LOG  = (long)NB * 16;

constexpr long OFF_XREV   = 0;
constexpr long OFF_XG_F   = OFF_XREV + SZ_XREV;
constexpr long OFF_XG_B   = OFF_XG_F + SZ_XG;
constexpr long OFF_GT_F   = OFF_XG_B + SZ_XG;
constexpr long OFF_GT_B   = OFF_GT_F + SZ_GT;
constexpr long OFF_HST    = OFF_GT_B + SZ_GT;      // 4 states: h_f, h_b, c_f, c_b
constexpr long OFF_HSEQ_F = OFF_HST + 4 * SZ_ST;
constexpr long OFF_HSEQ_B = OFF_HSEQ_F + SZ_SEQ;
constexpr long OFF_CSEQ_F = OFF_HSEQ_B + SZ_SEQ;
constexpr long OFF_CSEQ_B = OFF_CSEQ_F + SZ_SEQ;
constexpr long OFF_HBUF0  = OFF_CSEQ_B + SZ_SEQ;
constexpr long OFF_HBUF1  = OFF_HBUF0 + SZ_TREE;
constexpr long OFF_CBUF0  = OFF_HBUF1 + SZ_TREE;
constexpr long OFF_CBUF1  = OFF_CBUF0 + SZ_TREE;
constexpr long OFF_V      = OFF_CBUF1 + SZ_TREE;
constexpr long OFF_VP     = OFF_V + SZ_V;
constexpr long OFF_NH0    = OFF_VP + SZ_VP;
constexpr long OFF_NH1    = OFF_NH0 + SZ_NHC;
constexpr long OFF_NC0    = OFF_NH1 + SZ_NHC;
constexpr long OFF_NC1    = OFF_NC0 + SZ_NHC;
constexpr long OFF_LOG0   = OFF_NC1 + SZ_NHC;
constexpr long OFF_LOG1   = OFF_LOG0 + SZ_LOG;
constexpr long TOTAL_F    = OFF_LOG1 + SZ_LOG;

__device__ float g_buf[TOTAL_F];
__device__ int   g_sel[NB];
__device__ int   g_done[NB];
__device__ int   g_rowidx[512];
__device__ int   g_valid[512];
__device__ int   g_mr[512];

__device__ __forceinline__ float sigm(float x) { return 1.0f / (1.0f + expf(-x)); }

// ---------------- generic fp32 SGEMM body (double-buffered) ----------------
// C[r, n] = sum_{k in [kbeg,kend)} Arow(r)[k] * W[n, k]  (+ bias[n]) (+ Cinit[r, n])
// Arow(r) base:
//   rowIdx != null : A + rowIdx[r] * strideM
//   else           : A + (r / P) * strideB + (r % P) * strideM
// Tiles: 128x128x8, 8x8 per-thread, 256 threads. M,N multiples of 128; (kend-kbeg) mult of 8.
__device__ __forceinline__
void sgemm_body(const float* __restrict__ A, int P, long strideB, long strideM,
                const int* __restrict__ rowIdx,
                const float* __restrict__ W, int K, int kbeg, int kend,
                const float* __restrict__ bias,
                const float* __restrict__ Cinit, long ciStride,
                float* __restrict__ C, int N)
{
    __shared__ float As[2][8][128];
    __shared__ float Bs[2][8][128];
    const int tid = threadIdx.x;
    const int rowBase = blockIdx.y * 128;
    const int colBase = blockIdx.x * 128;
    const int tx = tid & 15;
    const int ty = tid >> 4;
    const int lr = tid >> 1;          // load row within tile (0..127)
    const int lk = (tid & 1) * 4;     // load k offset (0 or 4)

    const int r = rowBase + lr;
    const float* aPtr;
    if (rowIdx) {
        aPtr = A + (long)rowIdx[r] * strideM + kbeg + lk;
    } else {
        const int bidx = r / P;
        aPtr = A + (long)bidx * strideB + (long)(r - bidx * P) * strideM + kbeg + lk;
    }
    const float* wPtr = W + (long)(colBase + lr) * K + kbeg + lk;

    float acc[8][8];
#pragma unroll
    for (int i = 0; i < 8; i++)
#pragma unroll
        for (int j = 0; j < 8; j++) acc[i][j] = 0.0f;

    const int nk = (kend - kbeg) / 8;
    float4 av = *reinterpret_cast<const float4*>(aPtr);
    float4 bv = *reinterpret_cast<const float4*>(wPtr);
    int buf = 0;

    for (int it = 0; it < nk; it++) {
        As[buf][lk + 0][lr] = av.x; As[buf][lk + 1][lr] = av.y;
        As[buf][lk + 2][lr] = av.z; As[buf][lk + 3][lr] = av.w;
        Bs[buf][lk + 0][lr] = bv.x; Bs[buf][lk + 1][lr] = bv.y;
        Bs[buf][lk + 2][lr] = bv.z; Bs[buf][lk + 3][lr] = bv.w;
        __syncthreads();
        if (it + 1 < nk) {
            av = *reinterpret_cast<const float4*>(aPtr + (it + 1) * 8);
            bv = *reinterpret_cast<const float4*>(wPtr + (it + 1) * 8);
        }
#pragma unroll
        for (int kk = 0; kk < 8; kk++) {
            float4 a0 = *reinterpret_cast<const float4*>(&As[buf][kk][ty * 8]);
            float4 a1 = *reinterpret_cast<const float4*>(&As[buf][kk][ty * 8 + 4]);
            float4 b0 = *reinterpret_cast<const float4*>(&Bs[buf][kk][tx * 8]);
            float4 b1 = *reinterpret_cast<const float4*>(&Bs[buf][kk][tx * 8 + 4]);
            float ra[8] = {a0.x, a0.y, a0.z, a0.w, a1.x, a1.y, a1.z, a1.w};
            float rb[8] = {b0.x, b0.y, b0.z, b0.w, b1.x, b1.y, b1.z, b1.w};
#pragma unroll
            for (int i = 0; i < 8; i++)
#pragma unroll
                for (int j = 0; j < 8; j++)
                    acc[i][j] += ra[i] * rb[j];
        }
        buf ^= 1;
    }

#pragma unroll
    for (int i = 0; i < 8; i++) {
        const long row = rowBase + ty * 8 + i;
#pragma unroll
        for (int j = 0; j < 8; j += 4) {
            const int col = colBase + tx * 8 + j;
            float4 v;
            v.x = acc[i][j]; v.y = acc[i][j + 1]; v.z = acc[i][j + 2]; v.w = acc[i][j + 3];
            if (bias) {
                v.x += bias[col]; v.y += bias[col + 1];
                v.z += bias[col + 2]; v.w += bias[col + 3];
            }
            if (Cinit) {
                float4 ci = *reinterpret_cast<const float4*>(Cinit + row * ciStride + col);
                v.x += ci.x; v.y += ci.y; v.z += ci.z; v.w += ci.w;
            }
            *reinterpret_cast<float4*>(C + row * N + col) = v;
        }
    }
}

__global__ __launch_bounds__(256, 2)
void sgemm_k(const float* __restrict__ A, int P, long strideB, long strideM,
             const int* __restrict__ rowIdx,
             const float* __restrict__ W, int K,
             const float* __restrict__ bias,
             const float* __restrict__ Cinit, long ciStride,
             float* __restrict__ C, int N)
{
    sgemm_body(A, P, strideB, strideM, rowIdx, W, K, 0, K, bias, Cinit, ciStride, C, N);
}

// dual variant: blockIdx.z selects between two independent GEMMs of identical geometry
__global__ __launch_bounds__(256, 2)
void sgemm_dual_k(const float* __restrict__ A0, const float* __restrict__ A1,
                  int P, long strideB, long strideM,
                  const float* __restrict__ W0, const float* __restrict__ W1, int K,
                  const float* __restrict__ bias0, const float* __restrict__ bias1,
                  const float* __restrict__ Ci0, const float* __restrict__ Ci1, long ciStride,
                  float* __restrict__ C0, float* __restrict__ C1, int N)
{
    if (blockIdx.z == 0)
        sgemm_body(A0, P, strideB, strideM, nullptr, W0, K, 0, K, bias0, Ci0, ciStride, C0, N);
    else
        sgemm_body(A1, P, strideB, strideM, nullptr, W1, K, 0, K, bias1, Ci1, ciStride, C1, N);
}

// split-K variant for the incremental gather-GEMM: M=512 gathered rows, partial sums
// per split written to Cpart[split][512][NG5]; NO bias (added in the fused gate reduce).
__global__ __launch_bounds__(256, 2)
void sgemm_splitk_k(const float* __restrict__ A, long strideM,
                    const int* __restrict__ rowIdx,
                    const float* __restrict__ W, int K,
                    float* __restrict__ Cpart)
{
    const int sp = blockIdx.z;
    const int kb = sp * (K / NSPLIT);
    const int ke = kb + K / NSPLIT;
    sgemm_body(A, 1, 0, strideM, rowIdx, W, K, kb, ke, nullptr, nullptr, 0,
               Cpart + (long)sp * 512 * NG5, NG5);
}

// ---------------- helper kernels ----------------
__global__ void fill0_k(float* p, long n) {
    long i = (long)blockIdx.x * 256 + threadIdx.x;
    if (i < n) p[i] = 0.0f;
}

__global__ void rev_input_k(const float* __restrict__ x, const int* __restrict__ len,
                            float* __restrict__ xrev)
{
    int idx = blockIdx.x * 256 + threadIdx.x;        // NB*NL*NH
    int j = idx % NH;
    int t2 = idx / NH;
    int t = t2 % NL;
    int b = t2 / NL;
    int ln = len[b];
    int src = (t < ln) ? (ln - 1 - t) : t;
    xrev[idx] = x[((long)b * NL + src) * NH + j];
}

// fused fwd+bwd LSTM cell: idx covers 2*NB*NH, first half fwd
__global__ void lstm_cell2_k(const float* __restrict__ gf, const float* __restrict__ gb,
                             float* __restrict__ hf, float* __restrict__ hb,
                             float* __restrict__ cf, float* __restrict__ cb,
                             float* __restrict__ hsf, float* __restrict__ hsb,
                             float* __restrict__ csf, float* __restrict__ csb, int t)
{
    int gidx = blockIdx.x * 256 + threadIdx.x;       // 2*NB*NH
    int half = gidx >= NB * NH;
    int idx = gidx - half * NB * NH;
    int b = idx >> 9;
    int j = idx & (NH - 1);
    const float* g = (half ? gb : gf) + (long)b * NG4;
    float* hstate = half ? hb : hf;
    float* cstate = half ? cb : cf;
    float* hseq   = half ? hsb : hsf;
    float* cseq   = half ? csb : csf;
    float gi = g[j];
    float gfo = g[NH + j];
    float gu = g[2 * NH + j];
    float go = g[3 * NH + j];
    float c = sigm(gfo) * cstate[idx] + sigm(gi) * tanhf(gu);
    float h = sigm(go) * tanhf(c);
    cstate[idx] = c;
    hstate[idx] = h;
    long s = ((long)b * NL + t) * NH + j;
    hseq[s] = h;
    cseq[s] = c;
}

__global__ void tree_init_k(const float* __restrict__ hseqf, const float* __restrict__ hseqb,
                            const float* __restrict__ cseqf, const float* __restrict__ cseqb,
                            const int* __restrict__ len,
                            float* __restrict__ hbuf, float* __restrict__ cbuf)
{
    int idx = blockIdx.x * 256 + threadIdx.x;        // NB*NL*ND2
    int j = idx % ND2;
    int t2 = idx / ND2;
    int m = t2 % NL;
    int b = t2 / NL;
    float hv, cv;
    if (j < NH) {
        long s = ((long)b * NL + m) * NH + j;
        hv = hseqf[s]; cv = cseqf[s];
    } else {
        int ln = len[b];
        int rm = (m < ln) ? (ln - 1 - m) : m;
        long s = ((long)b * NL + rm) * NH + (j - NH);
        hv = hseqb[s]; cv = cseqb[s];
    }
    hbuf[idx] = hv;
    cbuf[idx] = cv;
}

// full per-pair gates + logits (iter 0 only). grid = NB*15 blocks.
__global__ void tree_gate_full_k(const float* __restrict__ v, const float* __restrict__ cbuf,
                                 float* __restrict__ nh, float* __restrict__ nc,
                                 float* __restrict__ logits, const float* __restrict__ wq)
{
    int blk = blockIdx.x;
    int b = blk / 15;
    int m = blk - b * 15;
    const float* vr = v + (long)blk * NG5;
    const float* cl = cbuf + ((long)b * NL + m) * ND2;
    const float* cr = cl + ND2;
    float* nhr = nh + ((long)b * 15 + m) * ND2;
    float* ncr = nc + ((long)b * 15 + m) * ND2;
    float dot = 0.0f;
    for (int d = threadIdx.x; d < ND2; d += 256) {
        float vi  = vr[d];
        float vfl = vr[ND2 + d];
        float vfr = vr[2 * ND2 + d];
        float vu  = vr[3 * ND2 + d];
        float vo  = vr[4 * ND2 + d];
        float c = cl[d] * sigm(vfl + 1.0f) + cr[d] * sigm(vfr + 1.0f) + tanhf(vu) * sigm(vi);
        float h = sigm(vo) * tanhf(c);
        ncr[d] = c;
        nhr[d] = h;
        dot += h * wq[d];
    }
    __shared__ float red[8];
#pragma unroll
    for (int o = 16; o > 0; o >>= 1) dot += __shfl_down_sync(0xffffffffu, dot, o);
    if ((threadIdx.x & 31) == 0) red[threadIdx.x >> 5] = dot;
    __syncthreads();
    if (threadIdx.x < 8) {
        float s = red[threadIdx.x];
#pragma unroll
        for (int o = 4; o > 0; o >>= 1) s += __shfl_down_sync(0xffu, s, o);
        if (threadIdx.x == 0) logits[b * 16 + m] = s;
    }
}

// incremental gates: fused split-K reduction + bias + gates + logit dot.
// grid = 512 blocks (r = b*2 + w), 256 threads. Deterministic (fixed split order).
__global__ void tree_gate_small_k(const float* __restrict__ vpart,
                                  const float* __restrict__ cbuf,
                                  float* __restrict__ nh, float* __restrict__ nc,
                                  float* __restrict__ logits, const float* __restrict__ wq,
                                  const float* __restrict__ bcomp,
                                  const int* __restrict__ valid, const int* __restrict__ mr)
{
    int r = blockIdx.x;
    if (!valid[r]) return;
    int b = r >> 1;
    int m = mr[r];
    const float* cl = cbuf + ((long)b * NL + m) * ND2;
    const float* cr = cl + ND2;
    float* nhr = nh + ((long)b * 15 + m) * ND2;
    float* ncr = nc + ((long)b * 15 + m) * ND2;
    float dot = 0.0f;
    for (int d = threadIdx.x; d < ND2; d += 256) {
        float g[5];
#pragma unroll
        for (int gg = 0; gg < 5; gg++) {
            long col = (long)gg * ND2 + d;
            float s = vpart[(long)r * NG5 + col];
#pragma unroll
            for (int sp = 1; sp < NSPLIT; sp++)
                s += vpart[((long)sp * 512 + r) * NG5 + col];
            g[gg] = s + bcomp[col];
        }
        float c = cl[d] * sigm(g[1] + 1.0f) + cr[d] * sigm(g[2] + 1.0f)
                + tanhf(g[3]) * sigm(g[0]);
        float h = sigm(g[4]) * tanhf(c);
        ncr[d] = c;
        nhr[d] = h;
        dot += h * wq[d];
    }
    __shared__ float red[8];
#pragma unroll
    for (int o = 16; o > 0; o >>= 1) dot += __shfl_down_sync(0xffffffffu, dot, o);
    if ((threadIdx.x & 31) == 0) red[threadIdx.x >> 5] = dot;
    __syncthreads();
    if (threadIdx.x < 8) {
        float s = red[threadIdx.x];
#pragma unroll
        for (int o = 4; o > 0; o >>= 1) s += __shfl_down_sync(0xffu, s, o);
        if (threadIdx.x == 0) logits[b * 16 + m] = s;
    }
}

// fused argmax + gather-row computation. one warp per batch element.
__global__ void argmax_rowoff_k(const float* __restrict__ logits, const int* __restrict__ len,
                                int* __restrict__ sel, int* __restrict__ done,
                                int* __restrict__ rowIdx, int* __restrict__ valid,
                                int* __restrict__ mr, int P, int iter)
{
    int b = blockIdx.x * 8 + (threadIdx.x >> 5);
    int lane = threadIdx.x & 31;
    if (b >= NB) return;
    int ln = len[b];
    float val = -3.4e38f;
    int idx = lane;
    if (lane < P) {
        val = logits[b * 16 + lane];
        if (iter + 1 + lane >= ln) val -= 10000.0f;   // matches ref masking exactly
    }
#pragma unroll
    for (int o = 16; o > 0; o >>= 1) {
        float ov = __shfl_down_sync(0xffffffffu, val, o);
        int oi = __shfl_down_sync(0xffffffffu, idx, o);
        if (ov > val || (ov == val && oi < idx)) { val = ov; idx = oi; }
    }
    idx = __shfl_sync(0xffffffffu, idx, 0);
    int dn = (iter + 1 < ln) ? 1 : 0;
    if (lane == 0) { sel[b] = idx; done[b] = dn; }
    if (lane < 2) {
        int newP = P - 1;
        int m = idx - 1 + lane;
        int v = (dn && m >= 0 && m <= newP - 1) ? 1 : 0;
        int hi = newP - 1 < 0 ? 0 : newP - 1;
        int mc = m < 0 ? 0 : (m > hi ? hi : m);
        int rr = b * 2 + lane;
        rowIdx[rr] = b * NL + mc;
        valid[rr] = v;
        mr[rr] = mc;
    }
}

// fused slot update + cache shift
__global__ void update_shift_k(const float* __restrict__ hold, const float* __restrict__ cold,
                               const float* __restrict__ nhc, const float* __restrict__ ncc,
                               const float* __restrict__ lgc,
                               float* __restrict__ hnew, float* __restrict__ cnew,
                               float* __restrict__ nhn, float* __restrict__ ncn,
                               float* __restrict__ lgn,
                               const int* __restrict__ sel, const int* __restrict__ done,
                               int P, int doShift)
{
    int idx = blockIdx.x * 256 + threadIdx.x;        // NB*P*ND2
    int d = idx % ND2;
    int t = idx / ND2;
    int m = t % P;
    int b = t / P;
    long obase = (long)b * NL * ND2;
    int dn = done[b];
    int s = sel[b];
    float hv, cv;
    if (!dn || m < s) {
        hv = hold[obase + (long)m * ND2 + d];
        cv = cold[obase + (long)m * ND2 + d];
    } else if (m == s) {
        long nidx = ((long)b * 15 + m) * ND2 + d;
        hv = nhc[nidx];
        cv = ncc[nidx];
    } else {
        hv = hold[obase + (long)(m + 1) * ND2 + d];
        cv = cold[obase + (long)(m + 1) * ND2 + d];
    }
    hnew[obase + (long)m * ND2 + d] = hv;
    cnew[obase + (long)m * ND2 + d] = cv;

    if (doShift && m < P - 1) {
        int src = (dn && m > s) ? m + 1 : m;
        long di = ((long)b * 15 + m) * ND2 + d;
        long si = ((long)b * 15 + src) * ND2 + d;
        nhn[di] = nhc[si];
        ncn[di] = ncc[si];
        if (d == 0) lgn[b * 16 + m] = lgc[b * 16 + src];
    }
}

__global__ void copy_out_k(const float* __restrict__ hfinal, float* __restrict__ out)
{
    int idx = blockIdx.x * 256 + threadIdx.x;        // NB*ND2
    int b = idx / ND2;
    int d = idx % ND2;
    out[idx] = hfinal[(long)b * NL * ND2 + d];
}

// ---------------- launch ----------------
extern "C" void kernel_launch(void* const* d_in, const int* in_sizes, int n_in,
                              void* d_out, int out_size)
{
    const float* x       = (const float*)d_in[0];
    const int*   len     = (const int*)d_in[1];
    const float* w_ih_f  = (const float*)d_in[2];
    const float* w_hh_f  = (const float*)d_in[3];
    const float* b_f     = (const float*)d_in[4];
    const float* w_ih_b  = (const float*)d_in[5];
    const float* w_hh_b  = (const float*)d_in[6];
    const float* b_b     = (const float*)d_in[7];
    const float* w_comp  = (const float*)d_in[8];
    const float* b_comp  = (const float*)d_in[9];
    const float* w_query = (const float*)d_in[10];
    float* out = (float*)d_out;

    float* S = nullptr;
    cudaGetSymbolAddress((void**)&S, g_buf);
    int* selp = nullptr;   cudaGetSymbolAddress((void**)&selp, g_sel);
    int* donep = nullptr;  cudaGetSymbolAddress((void**)&donep, g_done);
    int* rowp = nullptr;   cudaGetSymbolAddress((void**)&rowp, g_rowidx);
    int* valp = nullptr;   cudaGetSymbolAddress((void**)&valp, g_valid);
    int* mrp = nullptr;    cudaGetSymbolAddress((void**)&mrp, g_mr);

    // zero LSTM states (h_f, h_b, c_f, c_b)
    fill0_k<<<(int)((4 * SZ_ST + 255) / 256), 256>>>(S + OFF_HST, 4 * SZ_ST);

    // reversed input for backward LSTM
    rev_input_k<<<(NB * NL * NH) / 256, 256>>>(x, len, S + OFF_XREV);

    // fused input projections: xg = x @ w_ih^T + b   (M=4096, N=2048, K=512) x2
    dim3 gproj(NG4 / 128, (NB * NL) / 128, 2);
    sgemm_dual_k<<<gproj, 256>>>(x, S + OFF_XREV, 1, NH, NH,
                                 w_ih_f, w_ih_b, NH, b_f, b_b,
                                 nullptr, nullptr, 0,
                                 S + OFF_XG_F, S + OFF_XG_B, NG4);

    // recurrent steps (fwd+bwd fused per step)
    dim3 grec(NG4 / 128, NB / 128, 2);
    for (int t = 0; t < NL; t++) {
        sgemm_dual_k<<<grec, 256>>>(S + OFF_HST + 0 * SZ_ST, S + OFF_HST + 1 * SZ_ST,
                                    1, NH, NH,
                                    w_hh_f, w_hh_b, NH, nullptr, nullptr,
                                    S + OFF_XG_F + (long)t * NG4, S + OFF_XG_B + (long)t * NG4,
                                    (long)NL * NG4,
                                    S + OFF_GT_F, S + OFF_GT_B, NG4);
        lstm_cell2_k<<<(2 * NB * NH) / 256, 256>>>(S + OFF_GT_F, S + OFF_GT_B,
                                                   S + OFF_HST + 0 * SZ_ST, S + OFF_HST + 1 * SZ_ST,
                                                   S + OFF_HST + 2 * SZ_ST, S + OFF_HST + 3 * SZ_ST,
                                                   S + OFF_HSEQ_F, S + OFF_HSEQ_B,
                                                   S + OFF_CSEQ_F, S + OFF_CSEQ_B, t);
    }

    // init tree buffers: concat fwd + reversed bwd
    tree_init_k<<<(NB * NL * ND2) / 256, 256>>>(S + OFF_HSEQ_F, S + OFF_HSEQ_B,
                                                S + OFF_CSEQ_F, S + OFF_CSEQ_B,
                                                len, S + OFF_HBUF0, S + OFF_CBUF0);

    // iter-0 full pair GEMM + gates (15 pairs per batch)
    {
        dim3 gv(NG5 / 128, (NB * 15) / 128);
        sgemm_k<<<gv, 256>>>(S + OFF_HBUF0, 15, (long)NL * ND2, ND2, nullptr,
                             w_comp, NG4, b_comp, nullptr, 0, S + OFF_V, NG5);
        tree_gate_full_k<<<NB * 15, 256>>>(S + OFF_V, S + OFF_CBUF0,
                                           S + OFF_NH0, S + OFF_NC0, S + OFF_LOG0, w_query);
    }

    int cur = 0;   // slot buffer ping-pong
    int cc = 0;    // cache ping-pong
    for (int i = 0; i < 15; i++) {
        int P = 15 - i;
        float* hold = S + (cur ? OFF_HBUF1 : OFF_HBUF0);
        float* cold = S + (cur ? OFF_CBUF1 : OFF_CBUF0);
        float* hnew = S + (cur ? OFF_HBUF0 : OFF_HBUF1);
        float* cnew = S + (cur ? OFF_CBUF0 : OFF_CBUF1);
        float* nhc  = S + (cc ? OFF_NH1 : OFF_NH0);
        float* ncc  = S + (cc ? OFF_NC1 : OFF_NC0);
        float* lgc  = S + (cc ? OFF_LOG1 : OFF_LOG0);
        float* nhn  = S + (cc ? OFF_NH0 : OFF_NH1);
        float* ncn  = S + (cc ? OFF_NC0 : OFF_NC1);
        float* lgn  = S + (cc ? OFF_LOG0 : OFF_LOG1);

        int doShift = (i < 14) ? 1 : 0;
        argmax_rowoff_k<<<NB / 8, 256>>>(lgc, len, selp, donep, rowp, valp, mrp, P, i);
        update_shift_k<<<(NB * P * ND2) / 256, 256>>>(hold, cold, nhc, ncc, lgc,
                                                      hnew, cnew, nhn, ncn, lgn,
                                                      selp, donep, P, doShift);
        if (i < 14) {
            // incremental split-K GEMM over the ≤2 changed pairs per batch (M=512)
            dim3 gs(NG5 / 128, 512 / 128, NSPLIT);
            sgemm_splitk_k<<<gs, 256>>>(hnew, ND2, rowp, w_comp, NG4, S + OFF_VP);
            tree_gate_small_k<<<512, 256>>>(S + OFF_VP, cnew, nhn, ncn, lgn,
                                            w_query, b_comp, valp, mrp);
            cc ^= 1;
        }
        cur ^= 1;
    }

    copy_out_k<<<(NB * ND2) / 256, 256>>>(S + (cur ? OFF_HBUF1 : OFF_HBUF0), out);
}

// round 4
// speedup vs baseline: 3.8977x; 1.4190x over previous
#include <cuda_runtime.h>

// ---------------- problem constants ----------------
constexpr int NB  = 256;   // batch
constexpr int NL  = 16;    // max length
constexpr int NH  = 512;   // LSTM hidden
constexpr int ND2 = 1024;  // 2*NH
constexpr int NG4 = 2048;  // 4*NH (lstm gates) == 2*ND2
constexpr int NG5 = 5120;  // 5*ND2 (tree gates)
constexpr int NSLOT = 31;  // 16 initial + 15 created slots (stable ids)
constexpr int RSPLIT = 4;  // recurrent GEMM split-K
constexpr int ISPLIT = 4;  // incremental GEMM split-K

// ---------------- scratch layout ----------------
constexpr long SZ_XREV  = (long)NB * NL * NH;
constexpr long SZ_XG    = (long)NB * NL * NG4;
constexpr long SZ_GPART = (long)2 * RSPLIT * NB * NG4;
constexpr long SZ_ST    = (long)NB * NH;
constexpr long SZ_SEQ   = (long)NB * NL * NH;
constexpr long SZ_SLOT  = (long)NB * NSLOT * ND2;   // h_slot / c_slot / nh / nc
constexpr long SZ_P     = (long)NB * NSLOT * NG5;   // PL / PR
constexpr long SZ_LG    = (long)NB * NSLOT;
constexpr long SZ_VPART = (long)2 * ISPLIT * NB * NG5;

constexpr long OFF_XREV   = 0;
constexpr long OFF_XG_F   = OFF_XREV + SZ_XREV;
constexpr long OFF_XG_B   = OFF_XG_F + SZ_XG;
constexpr long OFF_GPART  = OFF_XG_B + SZ_XG;
constexpr long OFF_HST    = OFF_GPART + SZ_GPART;   // 4 states: h_f, h_b, c_f, c_b
constexpr long OFF_HSEQ_F = OFF_HST + 4 * SZ_ST;
constexpr long OFF_HSEQ_B = OFF_HSEQ_F + SZ_SEQ;
constexpr long OFF_CSEQ_F = OFF_HSEQ_B + SZ_SEQ;
constexpr long OFF_CSEQ_B = OFF_CSEQ_F + SZ_SEQ;
constexpr long OFF_HSLOT  = OFF_CSEQ_B + SZ_SEQ;
constexpr long OFF_CSLOT  = OFF_HSLOT + SZ_SLOT;
constexpr long OFF_NH     = OFF_CSLOT + SZ_SLOT;
constexpr long OFF_NC     = OFF_NH + SZ_SLOT;
constexpr long OFF_PL     = OFF_NC + SZ_SLOT;
constexpr long OFF_PR     = OFF_PL + SZ_P;
constexpr long OFF_LG     = OFF_PR + SZ_P;
constexpr long OFF_VPART  = OFF_LG + SZ_LG;
constexpr long TOTAL_F    = OFF_VPART + SZ_VPART;

__device__ float g_buf[TOTAL_F];
__device__ int   g_slotpos[NB * 16];   // position -> slot id
__device__ int   g_done[NB];
__device__ int   g_src[NB];            // selected pair's left slot id (merge source)
__device__ int   g_lid[NB];            // left-neighbor slot id for recompute pair (or -1)
__device__ int   g_rid[NB];            // right-neighbor slot id for recompute pair (or -1)

__device__ __forceinline__ float sigm(float x) { return 1.0f / (1.0f + expf(-x)); }

// ---------------- generic fp32 SGEMM body (double-buffered) ----------------
// C[row, col] = sum_{k in [kbeg,kend)} Arow(row)[k] * W[col, k]  (+ bias[col]) (+ Cinit)
// A row mapping:   bidx = row / P;  A + bidx*strideB + (row - bidx*P)*strideM + k
// W row stride = wstride (may exceed kend for column-sliced weights)
// C row mapping:   obid = row / P;  C + obid*coStrideB + (row - obid*P)*N + col
// Tiles 128x128x8, 8x8 per-thread, 256 threads. M,N tiles full; (kend-kbeg) mult of 8.
__device__ __forceinline__
void sgemm_body(const float* __restrict__ A, int P, long strideB, long strideM,
                const float* __restrict__ W, int wstride, int kbeg, int kend,
                const float* __restrict__ bias,
                const float* __restrict__ Cinit, long ciStride,
                float* __restrict__ C, int N, long coStrideB)
{
    __shared__ float As[2][8][128];
    __shared__ float Bs[2][8][128];
    const int tid = threadIdx.x;
    const int rowBase = blockIdx.y * 128;
    const int colBase = blockIdx.x * 128;
    const int tx = tid & 15;
    const int ty = tid >> 4;
    const int lr = tid >> 1;          // load row within tile (0..127)
    const int lk = (tid & 1) * 4;     // load k offset (0 or 4)

    const int r = rowBase + lr;
    const int bidx = r / P;
    const float* aPtr = A + (long)bidx * strideB + (long)(r - bidx * P) * strideM + kbeg + lk;
    const float* wPtr = W + (long)(colBase + lr) * wstride + kbeg + lk;

    float acc[8][8];
#pragma unroll
    for (int i = 0; i < 8; i++)
#pragma unroll
        for (int j = 0; j < 8; j++) acc[i][j] = 0.0f;

    const int nk = (kend - kbeg) / 8;
    float4 av = *reinterpret_cast<const float4*>(aPtr);
    float4 bv = *reinterpret_cast<const float4*>(wPtr);
    int buf = 0;

    for (int it = 0; it < nk; it++) {
        As[buf][lk + 0][lr] = av.x; As[buf][lk + 1][lr] = av.y;
        As[buf][lk + 2][lr] = av.z; As[buf][lk + 3][lr] = av.w;
        Bs[buf][lk + 0][lr] = bv.x; Bs[buf][lk + 1][lr] = bv.y;
        Bs[buf][lk + 2][lr] = bv.z; Bs[buf][lk + 3][lr] = bv.w;
        __syncthreads();
        if (it + 1 < nk) {
            av = *reinterpret_cast<const float4*>(aPtr + (it + 1) * 8);
            bv = *reinterpret_cast<const float4*>(wPtr + (it + 1) * 8);
        }
#pragma unroll
        for (int kk = 0; kk < 8; kk++) {
            float4 a0 = *reinterpret_cast<const float4*>(&As[buf][kk][ty * 8]);
            float4 a1 = *reinterpret_cast<const float4*>(&As[buf][kk][ty * 8 + 4]);
            float4 b0 = *reinterpret_cast<const float4*>(&Bs[buf][kk][tx * 8]);
            float4 b1 = *reinterpret_cast<const float4*>(&Bs[buf][kk][tx * 8 + 4]);
            float ra[8] = {a0.x, a0.y, a0.z, a0.w, a1.x, a1.y, a1.z, a1.w};
            float rb[8] = {b0.x, b0.y, b0.z, b0.w, b1.x, b1.y, b1.z, b1.w};
#pragma unroll
            for (int i = 0; i < 8; i++)
#pragma unroll
                for (int j = 0; j < 8; j++)
                    acc[i][j] += ra[i] * rb[j];
        }
        buf ^= 1;
    }

#pragma unroll
    for (int i = 0; i < 8; i++) {
        const int row = rowBase + ty * 8 + i;
        const int ob = row / P;
        const long rOff = (long)ob * coStrideB + (long)(row - ob * P) * N;
#pragma unroll
        for (int j = 0; j < 8; j += 4) {
            const int col = colBase + tx * 8 + j;
            float4 v;
            v.x = acc[i][j]; v.y = acc[i][j + 1]; v.z = acc[i][j + 2]; v.w = acc[i][j + 3];
            if (bias) {
                v.x += bias[col]; v.y += bias[col + 1];
                v.z += bias[col + 2]; v.w += bias[col + 3];
            }
            if (Cinit) {
                float4 ci = *reinterpret_cast<const float4*>(Cinit + (long)row * ciStride + col);
                v.x += ci.x; v.y += ci.y; v.z += ci.z; v.w += ci.w;
            }
            *reinterpret_cast<float4*>(C + rOff + col) = v;
        }
    }
}

// input projections: z selects fwd/bwd
__global__ __launch_bounds__(256, 2)
void sgemm_proj_k(const float* __restrict__ A0, const float* __restrict__ A1,
                  const float* __restrict__ W0, const float* __restrict__ W1,
                  const float* __restrict__ b0, const float* __restrict__ b1,
                  float* __restrict__ C0, float* __restrict__ C1)
{
    if (blockIdx.z == 0)
        sgemm_body(A0, 1, NH, 0, W0, NH, 0, NH, b0, nullptr, 0, C0, NG4, NG4);
    else
        sgemm_body(A1, 1, NH, 0, W1, NH, 0, NH, b1, nullptr, 0, C1, NG4, NG4);
}

// recurrent: z = dir*RSPLIT + sp, K=512 split into 128-chunks, partials out
__global__ __launch_bounds__(256, 2)
void sgemm_rec_k(const float* __restrict__ hf, const float* __restrict__ hb,
                 const float* __restrict__ whf, const float* __restrict__ whb,
                 float* __restrict__ gpart)
{
    const int z = blockIdx.z;
    const int dir = z / RSPLIT;
    const int sp = z % RSPLIT;
    const int kb = sp * (NH / RSPLIT);
    sgemm_body(dir ? hb : hf, 1, NH, 0, dir ? whb : whf, NH, kb, kb + NH / RSPLIT,
               nullptr, nullptr, 0, gpart + (long)z * NB * NG4, NG4, NG4);
}

// iter-0 slot partials: z = side (0 = PL, 1 = PR). M = NB*16 slot rows.
__global__ __launch_bounds__(256, 2)
void sgemm_slots0_k(const float* __restrict__ h_slot, const float* __restrict__ w_comp,
                    float* __restrict__ PL, float* __restrict__ PR)
{
    const int side = blockIdx.z;
    sgemm_body(h_slot, 16, (long)NSLOT * ND2, ND2,
               w_comp + side * ND2, NG4, 0, ND2,
               nullptr, nullptr, 0,
               side ? PR : PL, NG5, (long)NSLOT * NG5);
}

// incremental slot partials for the newly created slot. z = side*ISPLIT + sp.
__global__ __launch_bounds__(256, 2)
void sgemm_inc_k(const float* __restrict__ h_slot, const float* __restrict__ w_comp,
                 float* __restrict__ vpart, int newid)
{
    const int z = blockIdx.z;
    const int side = z / ISPLIT;
    const int sp = z % ISPLIT;
    const int kb = sp * (ND2 / ISPLIT);
    sgemm_body(h_slot + (long)newid * ND2, 1, (long)NSLOT * ND2, 0,
               w_comp + side * ND2, NG4, kb, kb + ND2 / ISPLIT,
               nullptr, nullptr, 0,
               vpart + (long)z * NB * NG5, NG5, NG5);
}

// ---------------- helper kernels ----------------
__global__ void fill0_k(float* p, long n) {
    long i = (long)blockIdx.x * 256 + threadIdx.x;
    if (i < n) p[i] = 0.0f;
}

__global__ void rev_input_k(const float* __restrict__ x, const int* __restrict__ len,
                            float* __restrict__ xrev)
{
    int idx = blockIdx.x * 256 + threadIdx.x;        // NB*NL*NH
    int j = idx % NH;
    int t2 = idx / NH;
    int t = t2 % NL;
    int b = t2 / NL;
    int ln = len[b];
    int src = (t < ln) ? (ln - 1 - t) : t;
    xrev[idx] = x[((long)b * NL + src) * NH + j];
}

// fused fwd+bwd LSTM cell with split-K partial reduction
__global__ void lstm_cell2_k(const float* __restrict__ xgf, const float* __restrict__ xgb,
                             const float* __restrict__ gpart,
                             float* __restrict__ hf, float* __restrict__ hb,
                             float* __restrict__ cf, float* __restrict__ cb,
                             float* __restrict__ hsf, float* __restrict__ hsb,
                             float* __restrict__ csf, float* __restrict__ csb, int t)
{
    int gidx = blockIdx.x * 256 + threadIdx.x;       // 2*NB*NH
    int dir = gidx >= NB * NH;
    int idx = gidx - dir * NB * NH;
    int b = idx >> 9;
    int j = idx & (NH - 1);
    const float* xg = (dir ? xgb : xgf) + (long)b * NL * NG4;
    const float* gp = gpart + (long)dir * RSPLIT * NB * NG4 + (long)b * NG4;
    float g[4];
#pragma unroll
    for (int c4 = 0; c4 < 4; c4++) {
        int comp = c4 * NH + j;
        float s = xg[comp];
#pragma unroll
        for (int sp = 0; sp < RSPLIT; sp++)
            s += gp[(long)sp * NB * NG4 + comp];
        g[c4] = s;
    }
    float* hstate = dir ? hb : hf;
    float* cstate = dir ? cb : cf;
    float* hseq   = dir ? hsb : hsf;
    float* cseq   = dir ? csb : csf;
    float c = sigm(g[1]) * cstate[idx] + sigm(g[0]) * tanhf(g[2]);
    float h = sigm(g[3]) * tanhf(c);
    cstate[idx] = c;
    hstate[idx] = h;
    long s = ((long)b * NL + t) * NH + j;
    hseq[s] = h;
    cseq[s] = c;
}

// init slot h/c (slots 0..15 = leaf positions) and position->slot map
__global__ void tree_init_k(const float* __restrict__ hseqf, const float* __restrict__ hseqb,
                            const float* __restrict__ cseqf, const float* __restrict__ cseqb,
                            const int* __restrict__ len,
                            float* __restrict__ h_slot, float* __restrict__ c_slot,
                            int* __restrict__ slotpos)
{
    int idx = blockIdx.x * 256 + threadIdx.x;        // NB*NL*ND2
    int j = idx % ND2;
    int t2 = idx / ND2;
    int m = t2 % NL;
    int b = t2 / NL;
    float hv, cv;
    if (j < NH) {
        long s = ((long)b * NL + m) * NH + j;
        hv = hseqf[s]; cv = cseqf[s];
    } else {
        int ln = len[b];
        int rm = (m < ln) ? (ln - 1 - m) : m;
        long s = ((long)b * NL + rm) * NH + (j - NH);
        hv = hseqb[s]; cv = cseqb[s];
    }
    long so = ((long)b * NSLOT + m) * ND2 + j;
    h_slot[so] = hv;
    c_slot[so] = cv;
    if (j == 0) slotpos[b * 16 + m] = m;
}

// iter-0 pair gates: v = PL[m] + PR[m+1] + bias. grid NB*15.
__global__ void gate_full0_k(const float* __restrict__ PL, const float* __restrict__ PR,
                             const float* __restrict__ c_slot,
                             const float* __restrict__ bcomp, const float* __restrict__ wq,
                             float* __restrict__ nh, float* __restrict__ nc,
                             float* __restrict__ lg)
{
    int blk = blockIdx.x;
    int b = blk / 15;
    int m = blk - b * 15;
    const float* pl = PL + ((long)b * NSLOT + m) * NG5;
    const float* pr = PR + ((long)b * NSLOT + m + 1) * NG5;
    const float* cl = c_slot + ((long)b * NSLOT + m) * ND2;
    const float* cr = cl + ND2;
    float* nhr = nh + ((long)b * NSLOT + m) * ND2;
    float* ncr = nc + ((long)b * NSLOT + m) * ND2;
    float dot = 0.0f;
    for (int d = threadIdx.x; d < ND2; d += 256) {
        float g[5];
#pragma unroll
        for (int gg = 0; gg < 5; gg++) {
            int col = gg * ND2 + d;
            g[gg] = pl[col] + pr[col] + bcomp[col];
        }
        float c = cl[d] * sigm(g[1] + 1.0f) + cr[d] * sigm(g[2] + 1.0f)
                + tanhf(g[3]) * sigm(g[0]);
        float h = sigm(g[4]) * tanhf(c);
        ncr[d] = c;
        nhr[d] = h;
        dot += h * wq[d];
    }
    __shared__ float red[8];
#pragma unroll
    for (int o = 16; o > 0; o >>= 1) dot += __shfl_down_sync(0xffffffffu, dot, o);
    if ((threadIdx.x & 31) == 0) red[threadIdx.x >> 5] = dot;
    __syncthreads();
    if (threadIdx.x < 8) {
        float s = red[threadIdx.x];
#pragma unroll
        for (int o = 4; o > 0; o >>= 1) s += __shfl_down_sync(0xffu, s, o);
        if (threadIdx.x == 0) lg[blk - b * 15 + (long)b * NSLOT] = s;
    }
}

// argmax over positions (gather logits via slotpos) + slotpos update + recompute descriptors
__global__ void argmax2_k(const float* __restrict__ lg, const int* __restrict__ len,
                          int* __restrict__ slotpos,
                          int* __restrict__ done, int* __restrict__ src,
                          int* __restrict__ lid, int* __restrict__ rid, int iter)
{
    int b = blockIdx.x * 8 + (threadIdx.x >> 5);
    int lane = threadIdx.x & 31;
    if (b >= NB) return;
    const int npairs = 15 - iter;
    const int nslots = 16 - iter;
    int ln = len[b];
    int myold = 0, mynext = 0;
    if (lane < nslots) myold = slotpos[b * 16 + lane];
    if (lane + 1 < nslots) mynext = slotpos[b * 16 + lane + 1];
    float val = -3.4e38f;
    int idx = lane;
    if (lane < npairs) {
        val = lg[(long)b * NSLOT + myold];
        if (iter + 1 + lane >= ln) val -= 10000.0f;   // matches ref masking exactly
    }
#pragma unroll
    for (int o = 16; o > 0; o >>= 1) {
        float ov = __shfl_down_sync(0xffffffffu, val, o);
        int oi = __shfl_down_sync(0xffffffffu, idx, o);
        if (ov > val || (ov == val && oi < idx)) { val = ov; idx = oi; }
    }
    int s = __shfl_sync(0xffffffffu, idx, 0);
    int dn = (iter + 1 < ln) ? 1 : 0;
    int srck = __shfl_sync(0xffffffffu, myold, s);
    int lidv = __shfl_sync(0xffffffffu, myold, (s >= 1) ? s - 1 : 0);
    int ridv = __shfl_sync(0xffffffffu, myold, (s + 2 <= nslots - 1) ? s + 2 : 0);
    int newid = 16 + iter;
    __syncwarp();
    if (dn && lane < nslots - 1) {
        int v = (lane < s) ? myold : ((lane == s) ? newid : mynext);
        slotpos[b * 16 + lane] = v;
    }
    if (lane == 0) {
        done[b] = dn;
        src[b]  = srck;
        lid[b]  = (dn && s >= 1) ? lidv : -1;
        rid[b]  = (dn && s + 2 <= nslots - 1) ? ridv : -1;
    }
}

// materialize the new slot's h/c from the selected pair's cache
__global__ void copy_new_k(const float* __restrict__ nh, const float* __restrict__ nc,
                           float* __restrict__ h_slot, float* __restrict__ c_slot,
                           const int* __restrict__ done, const int* __restrict__ src, int newid)
{
    int idx = blockIdx.x * 256 + threadIdx.x;        // NB*ND2
    int b = idx >> 10;
    int d = idx & (ND2 - 1);
    float hv = 0.0f, cv = 0.0f;
    if (done[b]) {
        long si = ((long)b * NSLOT + src[b]) * ND2 + d;
        hv = nh[si];
        cv = nc[si];
    }
    long di = ((long)b * NSLOT + newid) * ND2 + d;
    h_slot[di] = hv;
    c_slot[di] = cv;
}

// fused: reduce split-K partials -> PL/PR cache for new slot, then gate the (<=2) new pairs.
// grid 2*NB blocks: w=0 handles PR_new + pair (lid, new); w=1 handles PL_new + pair (new, rid).
__global__ void gate_small2_k(const float* __restrict__ vpart,
                              float* __restrict__ PL, float* __restrict__ PR,
                              const float* __restrict__ c_slot,
                              const float* __restrict__ bcomp, const float* __restrict__ wq,
                              float* __restrict__ nh, float* __restrict__ nc,
                              float* __restrict__ lg,
                              const int* __restrict__ done,
                              const int* __restrict__ lid, const int* __restrict__ rid,
                              int newid)
{
    __shared__ float vsh[NG5];
    int blk = blockIdx.x;
    int b = blk >> 1;
    int w = blk & 1;
    if (!done[b]) return;
    const int side = (w == 0) ? 1 : 0;   // w=0 computes PR side, w=1 PL side
    int pk = (w == 0) ? lid[b] : rid[b];
    const bool valid = (pk >= 0);
    int pkc = valid ? pk : 0;
    float* cacheDst = (w == 0 ? PR : PL) + ((long)b * NSLOT + newid) * NG5;
    const float* partner = (w == 0 ? PL : PR) + ((long)b * NSLOT + pkc) * NG5;
    const float* vp = vpart + ((long)side * ISPLIT * NB + b) * NG5;

    for (int col = threadIdx.x; col < NG5; col += 256) {
        float s = vp[col];
#pragma unroll
        for (int sp = 1; sp < ISPLIT; sp++)
            s += vp[(long)sp * NB * NG5 + col];
        cacheDst[col] = s;
        if (valid) vsh[col] = s + partner[col] + bcomp[col];
    }
    __syncthreads();
    if (!valid) return;

    int lslot = (w == 0) ? pk : newid;
    int rslot = (w == 0) ? newid : pk;
    int outkey = lslot;
    const float* cl = c_slot + ((long)b * NSLOT + lslot) * ND2;
    const float* cr = c_slot + ((long)b * NSLOT + rslot) * ND2;
    float* nhr = nh + ((long)b * NSLOT + outkey) * ND2;
    float* ncr = nc + ((long)b * NSLOT + outkey) * ND2;
    float dot = 0.0f;
    for (int d = threadIdx.x; d < ND2; d += 256) {
        float g0 = vsh[d];
        float g1 = vsh[ND2 + d];
        float g2 = vsh[2 * ND2 + d];
        float g3 = vsh[3 * ND2 + d];
        float g4 = vsh[4 * ND2 + d];
        float c = cl[d] * sigm(g1 + 1.0f) + cr[d] * sigm(g2 + 1.0f) + tanhf(g3) * sigm(g0);
        float h = sigm(g4) * tanhf(c);
        ncr[d] = c;
        nhr[d] = h;
        dot += h * wq[d];
    }
    __shared__ float red[8];
#pragma unroll
    for (int o = 16; o > 0; o >>= 1) dot += __shfl_down_sync(0xffffffffu, dot, o);
    if ((threadIdx.x & 31) == 0) red[threadIdx.x >> 5] = dot;
    __syncthreads();
    if (threadIdx.x < 8) {
        float s = red[threadIdx.x];
#pragma unroll
        for (int o = 4; o > 0; o >>= 1) s += __shfl_down_sync(0xffu, s, o);
        if (threadIdx.x == 0) lg[(long)b * NSLOT + outkey] = s;
    }
}

__global__ void copy_out2_k(const float* __restrict__ h_slot, const int* __restrict__ slotpos,
                            float* __restrict__ out)
{
    int idx = blockIdx.x * 256 + threadIdx.x;        // NB*ND2
    int b = idx >> 10;
    int d = idx & (ND2 - 1);
    int sp0 = slotpos[b * 16];
    out[idx] = h_slot[((long)b * NSLOT + sp0) * ND2 + d];
}

// ---------------- launch ----------------
extern "C" void kernel_launch(void* const* d_in, const int* in_sizes, int n_in,
                              void* d_out, int out_size)
{
    const float* x       = (const float*)d_in[0];
    const int*   len     = (const int*)d_in[1];
    const float* w_ih_f  = (const float*)d_in[2];
    const float* w_hh_f  = (const float*)d_in[3];
    const float* b_f     = (const float*)d_in[4];
    const float* w_ih_b  = (const float*)d_in[5];
    const float* w_hh_b  = (const float*)d_in[6];
    const float* b_b     = (const float*)d_in[7];
    const float* w_comp  = (const float*)d_in[8];
    const float* b_comp  = (const float*)d_in[9];
    const float* w_query = (const float*)d_in[10];
    float* out = (float*)d_out;

    float* S = nullptr;
    cudaGetSymbolAddress((void**)&S, g_buf);
    int* posp = nullptr;   cudaGetSymbolAddress((void**)&posp, g_slotpos);
    int* donep = nullptr;  cudaGetSymbolAddress((void**)&donep, g_done);
    int* srcp = nullptr;   cudaGetSymbolAddress((void**)&srcp, g_src);
    int* lidp = nullptr;   cudaGetSymbolAddress((void**)&lidp, g_lid);
    int* ridp = nullptr;   cudaGetSymbolAddress((void**)&ridp, g_rid);

    float* h_slot = S + OFF_HSLOT;
    float* c_slot = S + OFF_CSLOT;
    float* PLp = S + OFF_PL;
    float* PRp = S + OFF_PR;
    float* nhp = S + OFF_NH;
    float* ncp = S + OFF_NC;
    float* lgp = S + OFF_LG;
    float* vpart = S + OFF_VPART;

    // zero LSTM states (h_f, h_b, c_f, c_b)
    fill0_k<<<(int)((4 * SZ_ST + 255) / 256), 256>>>(S + OFF_HST, 4 * SZ_ST);

    // reversed input for backward LSTM
    rev_input_k<<<(NB * NL * NH) / 256, 256>>>(x, len, S + OFF_XREV);

    // input projections (fwd+bwd fused)
    dim3 gproj(NG4 / 128, (NB * NL) / 128, 2);
    sgemm_proj_k<<<gproj, 256>>>(x, S + OFF_XREV, w_ih_f, w_ih_b, b_f, b_b,
                                 S + OFF_XG_F, S + OFF_XG_B);

    // recurrent steps: split-K dual GEMM + fused reduce/cell
    dim3 grec(NG4 / 128, NB / 128, 2 * RSPLIT);
    for (int t = 0; t < NL; t++) {
        sgemm_rec_k<<<grec, 256>>>(S + OFF_HST + 0 * SZ_ST, S + OFF_HST + 1 * SZ_ST,
                                   w_hh_f, w_hh_b, S + OFF_GPART);
        lstm_cell2_k<<<(2 * NB * NH) / 256, 256>>>(S + OFF_XG_F + (long)t * NG4,
                                                   S + OFF_XG_B + (long)t * NG4,
                                                   S + OFF_GPART,
                                                   S + OFF_HST + 0 * SZ_ST, S + OFF_HST + 1 * SZ_ST,
                                                   S + OFF_HST + 2 * SZ_ST, S + OFF_HST + 3 * SZ_ST,
                                                   S + OFF_HSEQ_F, S + OFF_HSEQ_B,
                                                   S + OFF_CSEQ_F, S + OFF_CSEQ_B, t);
    }

    // leaf slots
    tree_init_k<<<(NB * NL * ND2) / 256, 256>>>(S + OFF_HSEQ_F, S + OFF_HSEQ_B,
                                                S + OFF_CSEQ_F, S + OFF_CSEQ_B,
                                                len, h_slot, c_slot, posp);

    // iter-0: slot partials (PL/PR for slots 0..15) + all-pair gates
    dim3 gs0(NG5 / 128, (NB * 16) / 128, 2);
    sgemm_slots0_k<<<gs0, 256>>>(h_slot, w_comp, PLp, PRp);
    gate_full0_k<<<NB * 15, 256>>>(PLp, PRp, c_slot, b_comp, w_query, nhp, ncp, lgp);

    for (int i = 0; i < 15; i++) {
        int newid = 16 + i;
        argmax2_k<<<NB / 8, 256>>>(lgp, len, posp, donep, srcp, lidp, ridp, i);
        copy_new_k<<<(NB * ND2) / 256, 256>>>(nhp, ncp, h_slot, c_slot, donep, srcp, newid);
        if (i < 14) {
            dim3 gi(NG5 / 128, NB / 128, 2 * ISPLIT);
            sgemm_inc_k<<<gi, 256>>>(h_slot, w_comp, vpart, newid);
            gate_small2_k<<<2 * NB, 256>>>(vpart, PLp, PRp, c_slot, b_comp, w_query,
                                           nhp, ncp, lgp, donep, lidp, ridp, newid);
        }
    }

    copy_out2_k<<<(NB * ND2) / 256, 256>>>(h_slot, posp, out);
}